// round 1
// baseline (speedup 1.0000x reference)
#include <cuda_runtime.h>
#include <cstddef>

// Problem constants
constexpr int Bn = 4, Tn = 2048, Cn = 1024, Hn = 16, Dn = 64;

// Scratch (device globals — no allocation allowed)
__device__ float g_Q[(size_t)Bn * Hn * Tn * Dn];      // 32 MB
__device__ float g_K[(size_t)Bn * Hn * Tn * Dn];      // 32 MB
__device__ float g_V[(size_t)Bn * Hn * Tn * Dn];      // 32 MB
__device__ float g_attn[(size_t)Bn * Tn * Cn];        // 32 MB, [B,T,C]

// ---------------------------------------------------------------------------
// GEMM: C[M,N] = A[M,K] @ B[K,N] + bias[N]
// MODE 0: A=x, B=W_attn (N=3072), epilogue scatters into g_Q/g_K/g_V [B,H,T,D]
// MODE 1: A=g_attn, B=W_proj (N=1024), epilogue writes d_out [B,T,C]
// 128x128x8 tiling, 256 threads, 8x8 register tiles.
// ---------------------------------------------------------------------------
template <int MODE>
__global__ __launch_bounds__(256, 2)
void gemm_kernel(const float* __restrict__ A, const float* __restrict__ Bm,
                 const float* __restrict__ bias, float* __restrict__ Cout)
{
    constexpr int N = (MODE == 0) ? 3 * Cn : Cn;
    constexpr int K = Cn;

    __shared__ float As[8][128];   // A tile, transposed: As[k][m]
    __shared__ float Bs[8][128];   // B tile: Bs[k][n]

    const int tid  = threadIdx.x;
    const int bm   = blockIdx.y * 128;
    const int bn   = blockIdx.x * 128;

    const int arow = tid >> 1;          // 0..127
    const int acol = (tid & 1) << 2;    // 0 or 4
    const int brow = tid >> 5;          // 0..7
    const int bcol = (tid & 31) << 2;   // 0..124

    const int ty = tid >> 4;            // 0..15 -> row block
    const int tx = tid & 15;            // 0..15 -> col block

    const float* Ap = A  + (size_t)(bm + arow) * K + acol;
    const float* Bp = Bm + (size_t)brow * N + bn + bcol;

    float acc[8][8];
    #pragma unroll
    for (int i = 0; i < 8; i++)
        #pragma unroll
        for (int j = 0; j < 8; j++) acc[i][j] = 0.0f;

    for (int k0 = 0; k0 < K; k0 += 8) {
        const float4 av = *(const float4*)Ap;
        const float4 bv = *(const float4*)Bp;
        Ap += 8;
        Bp += (size_t)8 * N;

        As[acol + 0][arow] = av.x;
        As[acol + 1][arow] = av.y;
        As[acol + 2][arow] = av.z;
        As[acol + 3][arow] = av.w;
        *(float4*)&Bs[brow][bcol] = bv;
        __syncthreads();

        #pragma unroll
        for (int kk = 0; kk < 8; kk++) {
            float a[8], b[8];
            *(float4*)&a[0] = *(const float4*)&As[kk][ty * 8];
            *(float4*)&a[4] = *(const float4*)&As[kk][ty * 8 + 4];
            *(float4*)&b[0] = *(const float4*)&Bs[kk][tx * 8];
            *(float4*)&b[4] = *(const float4*)&Bs[kk][tx * 8 + 4];
            #pragma unroll
            for (int i = 0; i < 8; i++)
                #pragma unroll
                for (int j = 0; j < 8; j++)
                    acc[i][j] = fmaf(a[i], b[j], acc[i][j]);
        }
        __syncthreads();
    }

    // Epilogue
    #pragma unroll
    for (int i = 0; i < 8; i++) {
        const int m = bm + ty * 8 + i;
        if (MODE == 1) {
            #pragma unroll
            for (int j4 = 0; j4 < 8; j4 += 4) {
                const int n = bn + tx * 8 + j4;
                float4 o;
                o.x = acc[i][j4 + 0] + bias[n + 0];
                o.y = acc[i][j4 + 1] + bias[n + 1];
                o.z = acc[i][j4 + 2] + bias[n + 2];
                o.w = acc[i][j4 + 3] + bias[n + 3];
                *(float4*)&Cout[(size_t)m * N + n] = o;
            }
        } else {
            const int bidx = m >> 11;       // / Tn
            const int t    = m & (Tn - 1);
            #pragma unroll
            for (int j4 = 0; j4 < 8; j4 += 4) {
                const int n    = bn + tx * 8 + j4;
                const int part = n >> 10;   // 0:Q 1:K 2:V
                const int c    = n & (Cn - 1);
                const int h    = c >> 6;
                const int d    = c & (Dn - 1);
                float* dst = (part == 0) ? g_Q : (part == 1) ? g_K : g_V;
                float4 o;
                o.x = acc[i][j4 + 0] + bias[n + 0];
                o.y = acc[i][j4 + 1] + bias[n + 1];
                o.z = acc[i][j4 + 2] + bias[n + 2];
                o.w = acc[i][j4 + 3] + bias[n + 3];
                *(float4*)&dst[((size_t)(bidx * Hn + h) * Tn + t) * Dn + d] = o;
            }
        }
    }
}

// ---------------------------------------------------------------------------
// Flash attention (causal), fp32.
// One block = 64 queries of one (b,h). K-tiles of 64 keys, online softmax.
// All 64x64 SMEM tiles XOR-swizzled: float4-column index ^= (row>>2)&15
// -> conflict-free float4 loads AND stores for every access pattern here.
// ---------------------------------------------------------------------------
__device__ __forceinline__ int swz4(int row, int col4)
{
    return (row << 4) + (col4 ^ ((row >> 2) & 15));   // index in float4 units
}

__global__ __launch_bounds__(256, 2)
void flash_kernel(const float* __restrict__ Q, const float* __restrict__ K,
                  const float* __restrict__ V, float* __restrict__ Out)
{
    extern __shared__ float sm[];
    float* Qs = sm;             // 4096 floats (64x64)
    float* Ks = sm + 4096;
    float* Vs = sm + 8192;
    float* Ps = sm + 12288;

    const int tid = threadIdx.x;
    const int qt = blockIdx.x, h = blockIdx.y, b = blockIdx.z;
    const int q0 = qt << 6;

    const size_t head_off = (size_t)((b * Hn + h) * Tn) * Dn;
    const float* Qg = Q + head_off + (size_t)q0 * Dn;
    const float* Kg = K + head_off;
    const float* Vg = V + head_off;

    const int ty = tid >> 4;    // 0..15: rows ty*4..ty*4+3
    const int tx = tid & 15;    // 0..15: cols tx*4..tx*4+3

    // Load Q tile (swizzled)
    #pragma unroll
    for (int i = 0; i < 4; i++) {
        const int e  = tid + (i << 8);
        const int r  = e >> 4;
        const int c4 = e & 15;
        *(float4*)(Qs + (swz4(r, c4) << 2)) =
            *(const float4*)(Qg + r * Dn + (c4 << 2));
    }

    float m_i[4], l_i[4], acc[4][4];
    #pragma unroll
    for (int i = 0; i < 4; i++) {
        m_i[i] = -1e30f;
        l_i[i] = 0.0f;
        #pragma unroll
        for (int j = 0; j < 4; j++) acc[i][j] = 0.0f;
    }

    for (int kt = 0; kt <= qt; kt++) {
        // Load K and V tiles (swizzled)
        #pragma unroll
        for (int i = 0; i < 4; i++) {
            const int e  = tid + (i << 8);
            const int r  = e >> 4;
            const int c4 = e & 15;
            const int go = (kt * 64 + r) * Dn + (c4 << 2);
            *(float4*)(Ks + (swz4(r, c4) << 2)) = *(const float4*)(Kg + go);
            *(float4*)(Vs + (swz4(r, c4) << 2)) = *(const float4*)(Vg + go);
        }
        __syncthreads();

        // S = Q K^T (4x4 per thread)
        float s[4][4];
        #pragma unroll
        for (int i = 0; i < 4; i++)
            #pragma unroll
            for (int j = 0; j < 4; j++) s[i][j] = 0.0f;

        #pragma unroll
        for (int d4 = 0; d4 < 16; d4++) {
            float4 a[4], bb[4];
            #pragma unroll
            for (int i = 0; i < 4; i++)
                a[i] = *(const float4*)(Qs + (swz4(ty * 4 + i, d4) << 2));
            #pragma unroll
            for (int j = 0; j < 4; j++)
                bb[j] = *(const float4*)(Ks + (swz4(tx * 4 + j, d4) << 2));
            #pragma unroll
            for (int i = 0; i < 4; i++)
                #pragma unroll
                for (int j = 0; j < 4; j++)
                    s[i][j] += a[i].x * bb[j].x + a[i].y * bb[j].y +
                               a[i].z * bb[j].z + a[i].w * bb[j].w;
        }

        // Scale + causal mask (only diagonal tile needs it)
        const bool diag = (kt == qt);
        #pragma unroll
        for (int i = 0; i < 4; i++)
            #pragma unroll
            for (int j = 0; j < 4; j++) {
                s[i][j] *= 0.125f;                       // 1/sqrt(64)
                if (diag && (tx * 4 + j) > (ty * 4 + i)) s[i][j] = -1e30f;
            }

        // Row max (reduce across the 16 tx-threads of the row group)
        float rmax[4];
        #pragma unroll
        for (int i = 0; i < 4; i++)
            rmax[i] = fmaxf(fmaxf(s[i][0], s[i][1]), fmaxf(s[i][2], s[i][3]));
        #pragma unroll
        for (int off = 1; off < 16; off <<= 1)
            #pragma unroll
            for (int i = 0; i < 4; i++)
                rmax[i] = fmaxf(rmax[i], __shfl_xor_sync(0xffffffffu, rmax[i], off));

        float alpha[4];
        #pragma unroll
        for (int i = 0; i < 4; i++) {
            const float mn = fmaxf(m_i[i], rmax[i]);
            alpha[i] = __expf(m_i[i] - mn);
            m_i[i]   = mn;
        }

        // P = exp(S - m), row sums
        float rsum[4];
        #pragma unroll
        for (int i = 0; i < 4; i++) {
            rsum[i] = 0.0f;
            #pragma unroll
            for (int j = 0; j < 4; j++) {
                const float p = __expf(s[i][j] - m_i[i]);
                s[i][j] = p;
                rsum[i] += p;
            }
        }
        #pragma unroll
        for (int off = 1; off < 16; off <<= 1)
            #pragma unroll
            for (int i = 0; i < 4; i++)
                rsum[i] += __shfl_xor_sync(0xffffffffu, rsum[i], off);

        #pragma unroll
        for (int i = 0; i < 4; i++) {
            l_i[i] = l_i[i] * alpha[i] + rsum[i];
            #pragma unroll
            for (int j = 0; j < 4; j++) acc[i][j] *= alpha[i];
        }

        // Write P (swizzled), then O += P @ V
        #pragma unroll
        for (int i = 0; i < 4; i++) {
            const float4 pv = make_float4(s[i][0], s[i][1], s[i][2], s[i][3]);
            *(float4*)(Ps + (swz4(ty * 4 + i, tx) << 2)) = pv;
        }
        __syncthreads();

        #pragma unroll
        for (int k4 = 0; k4 < 16; k4++) {
            float4 a[4], bb[4];
            #pragma unroll
            for (int i = 0; i < 4; i++)
                a[i] = *(const float4*)(Ps + (swz4(ty * 4 + i, k4) << 2));
            #pragma unroll
            for (int jj = 0; jj < 4; jj++)
                bb[jj] = *(const float4*)(Vs + (swz4(k4 * 4 + jj, tx) << 2));
            #pragma unroll
            for (int i = 0; i < 4; i++) {
                acc[i][0] += a[i].x * bb[0].x + a[i].y * bb[1].x + a[i].z * bb[2].x + a[i].w * bb[3].x;
                acc[i][1] += a[i].x * bb[0].y + a[i].y * bb[1].y + a[i].z * bb[2].y + a[i].w * bb[3].y;
                acc[i][2] += a[i].x * bb[0].z + a[i].y * bb[1].z + a[i].z * bb[2].z + a[i].w * bb[3].z;
                acc[i][3] += a[i].x * bb[0].w + a[i].y * bb[1].w + a[i].z * bb[2].w + a[i].w * bb[3].w;
            }
        }
        __syncthreads();
    }

    // Normalize and write to attn scratch in [B,T,C] layout
    float* Og = Out + ((size_t)(b * Tn + q0)) * Cn + h * Dn;
    #pragma unroll
    for (int i = 0; i < 4; i++) {
        const float inv = 1.0f / l_i[i];
        const float4 o = make_float4(acc[i][0] * inv, acc[i][1] * inv,
                                     acc[i][2] * inv, acc[i][3] * inv);
        *(float4*)(Og + (size_t)(ty * 4 + i) * Cn + (tx << 2)) = o;
    }
}

// ---------------------------------------------------------------------------
// Launch
// ---------------------------------------------------------------------------
extern "C" void kernel_launch(void* const* d_in, const int* in_sizes, int n_in,
                              void* d_out, int out_size)
{
    const float* x      = (const float*)d_in[0];
    const float* W_attn = (const float*)d_in[1];
    const float* b_attn = (const float*)d_in[2];
    const float* W_proj = (const float*)d_in[3];
    const float* b_proj = (const float*)d_in[4];
    float* out = (float*)d_out;

    float *Qp, *Kp, *Vp, *Ap;
    cudaGetSymbolAddress((void**)&Qp, g_Q);
    cudaGetSymbolAddress((void**)&Kp, g_K);
    cudaGetSymbolAddress((void**)&Vp, g_V);
    cudaGetSymbolAddress((void**)&Ap, g_attn);

    // 1) QKV projection, scattered into Q/K/V [B,H,T,D]
    {
        dim3 grid(3 * Cn / 128, (Bn * Tn) / 128);   // (24, 64)
        gemm_kernel<0><<<grid, 256>>>(x, W_attn, b_attn, nullptr);
    }

    // 2) Causal flash attention -> g_attn [B,T,C]
    {
        const int smem = 4 * 64 * 64 * (int)sizeof(float);   // 64 KB
        cudaFuncSetAttribute(flash_kernel,
                             cudaFuncAttributeMaxDynamicSharedMemorySize, smem);
        dim3 grid(Tn / 64, Hn, Bn);                 // (32, 16, 4)
        flash_kernel<<<grid, 256, smem>>>(Qp, Kp, Vp, Ap);
    }

    // 3) Output projection -> d_out
    {
        dim3 grid(Cn / 128, (Bn * Tn) / 128);       // (8, 64)
        gemm_kernel<1><<<grid, 256>>>(Ap, W_proj, b_proj, out);
    }
}

// round 3
// speedup vs baseline: 1.4626x; 1.4626x over previous
#include <cuda_runtime.h>
#include <cuda_bf16.h>
#include <cstdint>
#include <cstddef>

// Problem constants
constexpr int Bn = 4, Tn = 2048, Cn = 1024, Hn = 16, Dn = 64;
constexpr int Mr = Bn * Tn;      // 8192 rows
constexpr int K3 = 3 * Cn;       // 3072 = split-K (hi|lo|hi)
constexpr int NCH = K3 / 32;     // 96 K-chunks of 32 bf16

// Scratch (device globals — no allocation allowed)
__device__ float g_Q[(size_t)Bn * Hn * Tn * Dn];
__device__ float g_K[(size_t)Bn * Hn * Tn * Dn];
__device__ float g_V[(size_t)Bn * Hn * Tn * Dn];
__device__ __nv_bfloat16 g_A1[(size_t)Mr * K3];          // split x
__device__ __nv_bfloat16 g_B1[(size_t)(3 * Cn) * K3];    // split W_attn^T [N,K']
__device__ __nv_bfloat16 g_A2[(size_t)Mr * K3];          // split attn out
__device__ __nv_bfloat16 g_B2[(size_t)Cn * K3];          // split W_proj^T [N,K']

// ---------------------------------------------------------------------------
// Helpers (portable ISA only: mma.sync / ldmatrix / cp.async)
// ---------------------------------------------------------------------------
__device__ __forceinline__ uint32_t smem_u32(const void* p) {
    uint32_t a;
    asm("{ .reg .u64 t; cvta.to.shared.u64 t, %1; cvt.u32.u64 %0, t; }"
        : "=r"(a) : "l"(p));
    return a;
}

__device__ __forceinline__ void cp_async16(uint32_t dst, const void* src) {
    asm volatile("cp.async.cg.shared.global [%0], [%1], 16;"
                 :: "r"(dst), "l"(src) : "memory");
}
__device__ __forceinline__ void cp_commit() {
    asm volatile("cp.async.commit_group;" ::: "memory");
}
__device__ __forceinline__ void cp_wait1() {
    asm volatile("cp.async.wait_group 1;" ::: "memory");
}

__device__ __forceinline__ void ldsm4(uint32_t* r, uint32_t addr) {
    asm volatile("ldmatrix.sync.aligned.m8n8.x4.shared.b16 {%0,%1,%2,%3}, [%4];"
                 : "=r"(r[0]), "=r"(r[1]), "=r"(r[2]), "=r"(r[3]) : "r"(addr));
}

__device__ __forceinline__ void mma16816(float* c, const uint32_t* a, const uint32_t* b) {
    asm volatile(
        "mma.sync.aligned.m16n8k16.row.col.f32.bf16.bf16.f32 "
        "{%0,%1,%2,%3}, {%4,%5,%6,%7}, {%8,%9}, {%0,%1,%2,%3};"
        : "+f"(c[0]), "+f"(c[1]), "+f"(c[2]), "+f"(c[3])
        : "r"(a[0]), "r"(a[1]), "r"(a[2]), "r"(a[3]), "r"(b[0]), "r"(b[1]));
}

__device__ __forceinline__ void split2(float v, __nv_bfloat16& h, __nv_bfloat16& l) {
    h = __float2bfloat16_rn(v);
    l = __float2bfloat16_rn(v - __bfloat162float(h));
}
__device__ __forceinline__ uint32_t pk2(__nv_bfloat16 a, __nv_bfloat16 b) {
    __nv_bfloat162 t = __halves2bfloat162(a, b);
    return reinterpret_cast<uint32_t&>(t);
}

// Swizzled byte offset of 16B granule g (0..3) in row `row` of a [128 x 32]bf16
// tile stored as 128B lines of 2 rows. Conflict-free for cp.async stores and
// ldmatrix.x4 reads (verified over all granule phases).
__device__ __forceinline__ uint32_t tswz(int row, int g) {
    const uint32_t line = (uint32_t)(row >> 1);
    const uint32_t gr8  = (uint32_t)(((row & 1) << 2) | g);
    return (line * 8 + (gr8 ^ (line & 7))) * 16;
}

// ---------------------------------------------------------------------------
// Prep: split x [Mr, Cn] fp32 -> A' [Mr, 3K] bf16  (hi | lo | hi)
// ---------------------------------------------------------------------------
__global__ void split_x_kernel(const float* __restrict__ x, __nv_bfloat16* __restrict__ A)
{
    const size_t gid = (size_t)blockIdx.x * 256 + threadIdx.x;
    const size_t f = gid * 4;
    const int m = (int)(f >> 10);
    const int c = (int)(f & 1023);
    const float4 v = *(const float4*)(x + f);
    __nv_bfloat16 h0, h1, h2, h3, l0, l1, l2, l3;
    split2(v.x, h0, l0); split2(v.y, h1, l1);
    split2(v.z, h2, l2); split2(v.w, h3, l3);
    uint2 hiU = make_uint2(pk2(h0, h1), pk2(h2, h3));
    uint2 loU = make_uint2(pk2(l0, l1), pk2(l2, l3));
    __nv_bfloat16* p = A + (size_t)m * K3 + c;
    *(uint2*)p          = hiU;
    *(uint2*)(p + 1024) = loU;
    *(uint2*)(p + 2048) = hiU;
}

// ---------------------------------------------------------------------------
// Prep: transpose-split W [K=1024, N] fp32 -> B' [N, 3K] bf16  (hi | hi | lo)
// ---------------------------------------------------------------------------
__global__ void tsplit_kernel(const float* __restrict__ W, __nv_bfloat16* __restrict__ Bp, int N)
{
    __shared__ float sm[32][33];
    const int k0 = blockIdx.x * 32, n0 = blockIdx.y * 32;
    const int tx = threadIdx.x, ty = threadIdx.y;
    #pragma unroll
    for (int r = 0; r < 4; r++)
        sm[ty + r * 8][tx] = W[(size_t)(k0 + ty + r * 8) * N + n0 + tx];
    __syncthreads();
    #pragma unroll
    for (int r = 0; r < 4; r++) {
        const int n = n0 + ty + r * 8, k = k0 + tx;
        const float v = sm[tx][ty + r * 8];
        __nv_bfloat16 h, l; split2(v, h, l);
        __nv_bfloat16* p = Bp + (size_t)n * K3 + k;
        p[0] = h; p[1024] = h; p[2048] = l;
    }
}

// ---------------------------------------------------------------------------
// mma.sync GEMM: D[m,n] = sum_k' A'[m,k'] B'[n,k'] + bias[n]
// 128x128 CTA tile, BK=32, 8 warps (2x4), warp tile 64x32, 3-stage cp.async.
// MODE 0: scatter to g_Q/g_K/g_V.  MODE 1: write Cout [Mr, Cn].
// ---------------------------------------------------------------------------
template <int MODE>
__global__ __launch_bounds__(256, 2)
void gemm_mma(const __nv_bfloat16* __restrict__ A, const __nv_bfloat16* __restrict__ Bm,
              const float* __restrict__ bias, float* __restrict__ Cout)
{
    __shared__ __align__(1024) char smem[3 * 16384];   // 3 stages x (8KB A + 8KB B)
    const uint32_t sb = smem_u32(smem);

    const int tid  = threadIdx.x;
    const int lane = tid & 31;
    const int w    = tid >> 5;
    const int wm   = (w & 1) * 64;     // warp m offset
    const int wn   = (w >> 1) * 32;    // warp n offset
    const int bm   = blockIdx.y << 7;
    const int bn   = blockIdx.x << 7;

    // Per-thread gmem->smem assignment: row = tid>>1, granules (tid&1)*2, +1
    const int lrow = tid >> 1;
    const int lg   = (tid & 1) << 1;
    const __nv_bfloat16* gA = A  + (size_t)(bm + lrow) * K3 + lg * 8;
    const __nv_bfloat16* gB = Bm + (size_t)(bn + lrow) * K3 + lg * 8;
    const uint32_t dA0 = tswz(lrow, lg), dA1 = tswz(lrow, lg + 1);

    auto load_stage = [&](int stage, int ic) {
        const uint32_t aBase = sb + stage * 16384;
        const uint32_t bBase = aBase + 8192;
        const int koff = ic * 32;
        cp_async16(aBase + dA0, gA + koff);
        cp_async16(aBase + dA1, gA + koff + 8);
        cp_async16(bBase + dA0, gB + koff);
        cp_async16(bBase + dA1, gB + koff + 8);
    };

    float acc[4][4][4];
    #pragma unroll
    for (int i = 0; i < 4; i++)
        #pragma unroll
        for (int j = 0; j < 4; j++)
            #pragma unroll
            for (int r = 0; r < 4; r++) acc[i][j][r] = 0.0f;

    load_stage(0, 0); cp_commit();
    load_stage(1, 1); cp_commit();

    // ldmatrix lane addressing (within a stage)
    const int aRow = (lane & 15);              // + tile base
    const int aG   = (lane >> 4);              // + 2*kstep
    const int bRow = (lane & 7) + ((lane >> 4) << 3);
    const int bG   = ((lane >> 3) & 1);        // + 2*kstep

    for (int ic = 0; ic < NCH; ic++) {
        const int s = ic % 3;
        cp_wait1();
        __syncthreads();
        if (ic + 2 < NCH) load_stage((ic + 2) % 3, ic + 2);
        cp_commit();

        const uint32_t aBase = sb + s * 16384;
        const uint32_t bBase = aBase + 8192;

        #pragma unroll
        for (int ks = 0; ks < 2; ks++) {
            uint32_t af[4][4], bf[2][4];
            #pragma unroll
            for (int tm = 0; tm < 4; tm++)
                ldsm4(af[tm], aBase + tswz(wm + tm * 16 + aRow, ks * 2 + aG));
            #pragma unroll
            for (int tp = 0; tp < 2; tp++)
                ldsm4(bf[tp], bBase + tswz(wn + tp * 16 + bRow, ks * 2 + bG));
            #pragma unroll
            for (int tm = 0; tm < 4; tm++)
                #pragma unroll
                for (int tn = 0; tn < 4; tn++)
                    mma16816(acc[tm][tn], af[tm], &bf[tn >> 1][(tn & 1) * 2]);
        }
        __syncthreads();
    }

    // Epilogue
    const int gq = lane >> 2;          // row within 8
    const int t4 = lane & 3;           // col pair
    #pragma unroll
    for (int tm = 0; tm < 4; tm++) {
        #pragma unroll
        for (int tn = 0; tn < 4; tn++) {
            const int n = bn + wn + tn * 8 + t4 * 2;
            const float2 bv = *(const float2*)(bias + n);
            #pragma unroll
            for (int half = 0; half < 2; half++) {
                const int m = bm + wm + tm * 16 + gq + half * 8;
                float2 o;
                o.x = acc[tm][tn][half * 2 + 0] + bv.x;
                o.y = acc[tm][tn][half * 2 + 1] + bv.y;
                if (MODE == 1) {
                    *(float2*)(Cout + (size_t)m * Cn + n) = o;
                } else {
                    const int part = n >> 10, c = n & 1023, h = c >> 6, d = c & 63;
                    const int b2 = m >> 11, t = m & 2047;
                    float* dst = (part == 0) ? g_Q : (part == 1) ? g_K : g_V;
                    *(float2*)(dst + ((size_t)((b2 * Hn + h) * Tn + t)) * Dn + d) = o;
                }
            }
        }
    }
}

// ---------------------------------------------------------------------------
// Flash attention (causal), fp32 compute; epilogue writes split-bf16 A2'
// ---------------------------------------------------------------------------
__device__ __forceinline__ int swz4(int row, int col4)
{
    return (row << 4) + (col4 ^ ((row >> 2) & 15));
}

__global__ __launch_bounds__(256, 2)
void flash_kernel(const float* __restrict__ Q, const float* __restrict__ K,
                  const float* __restrict__ V, __nv_bfloat16* __restrict__ Out)
{
    extern __shared__ float sm[];
    float* Qs = sm;
    float* Ks = sm + 4096;
    float* Vs = sm + 8192;
    float* Ps = sm + 12288;

    const int tid = threadIdx.x;
    const int qt = blockIdx.x, h = blockIdx.y, b = blockIdx.z;
    const int q0 = qt << 6;

    const size_t head_off = (size_t)((b * Hn + h) * Tn) * Dn;
    const float* Qg = Q + head_off + (size_t)q0 * Dn;
    const float* Kg = K + head_off;
    const float* Vg = V + head_off;

    const int ty = tid >> 4;
    const int tx = tid & 15;

    #pragma unroll
    for (int i = 0; i < 4; i++) {
        const int e = tid + (i << 8);
        const int r = e >> 4, c4 = e & 15;
        *(float4*)(Qs + (swz4(r, c4) << 2)) = *(const float4*)(Qg + r * Dn + (c4 << 2));
    }

    float m_i[4], l_i[4], acc[4][4];
    #pragma unroll
    for (int i = 0; i < 4; i++) {
        m_i[i] = -1e30f; l_i[i] = 0.0f;
        #pragma unroll
        for (int j = 0; j < 4; j++) acc[i][j] = 0.0f;
    }

    for (int kt = 0; kt <= qt; kt++) {
        #pragma unroll
        for (int i = 0; i < 4; i++) {
            const int e = tid + (i << 8);
            const int r = e >> 4, c4 = e & 15;
            const int go = (kt * 64 + r) * Dn + (c4 << 2);
            *(float4*)(Ks + (swz4(r, c4) << 2)) = *(const float4*)(Kg + go);
            *(float4*)(Vs + (swz4(r, c4) << 2)) = *(const float4*)(Vg + go);
        }
        __syncthreads();

        float s[4][4];
        #pragma unroll
        for (int i = 0; i < 4; i++)
            #pragma unroll
            for (int j = 0; j < 4; j++) s[i][j] = 0.0f;

        #pragma unroll
        for (int d4 = 0; d4 < 16; d4++) {
            float4 a[4], bb[4];
            #pragma unroll
            for (int i = 0; i < 4; i++)
                a[i] = *(const float4*)(Qs + (swz4(ty * 4 + i, d4) << 2));
            #pragma unroll
            for (int j = 0; j < 4; j++)
                bb[j] = *(const float4*)(Ks + (swz4(tx * 4 + j, d4) << 2));
            #pragma unroll
            for (int i = 0; i < 4; i++)
                #pragma unroll
                for (int j = 0; j < 4; j++)
                    s[i][j] += a[i].x * bb[j].x + a[i].y * bb[j].y +
                               a[i].z * bb[j].z + a[i].w * bb[j].w;
        }

        const bool diag = (kt == qt);
        #pragma unroll
        for (int i = 0; i < 4; i++)
            #pragma unroll
            for (int j = 0; j < 4; j++) {
                s[i][j] *= 0.125f;
                if (diag && (tx * 4 + j) > (ty * 4 + i)) s[i][j] = -1e30f;
            }

        float rmax[4];
        #pragma unroll
        for (int i = 0; i < 4; i++)
            rmax[i] = fmaxf(fmaxf(s[i][0], s[i][1]), fmaxf(s[i][2], s[i][3]));
        #pragma unroll
        for (int off = 1; off < 16; off <<= 1)
            #pragma unroll
            for (int i = 0; i < 4; i++)
                rmax[i] = fmaxf(rmax[i], __shfl_xor_sync(0xffffffffu, rmax[i], off));

        float alpha[4];
        #pragma unroll
        for (int i = 0; i < 4; i++) {
            const float mn = fmaxf(m_i[i], rmax[i]);
            alpha[i] = __expf(m_i[i] - mn);
            m_i[i] = mn;
        }

        float rsum[4];
        #pragma unroll
        for (int i = 0; i < 4; i++) {
            rsum[i] = 0.0f;
            #pragma unroll
            for (int j = 0; j < 4; j++) {
                const float p = __expf(s[i][j] - m_i[i]);
                s[i][j] = p;
                rsum[i] += p;
            }
        }
        #pragma unroll
        for (int off = 1; off < 16; off <<= 1)
            #pragma unroll
            for (int i = 0; i < 4; i++)
                rsum[i] += __shfl_xor_sync(0xffffffffu, rsum[i], off);

        #pragma unroll
        for (int i = 0; i < 4; i++) {
            l_i[i] = l_i[i] * alpha[i] + rsum[i];
            #pragma unroll
            for (int j = 0; j < 4; j++) acc[i][j] *= alpha[i];
        }

        #pragma unroll
        for (int i = 0; i < 4; i++) {
            const float4 pv = make_float4(s[i][0], s[i][1], s[i][2], s[i][3]);
            *(float4*)(Ps + (swz4(ty * 4 + i, tx) << 2)) = pv;
        }
        __syncthreads();

        #pragma unroll
        for (int k4 = 0; k4 < 16; k4++) {
            float4 a[4], bb[4];
            #pragma unroll
            for (int i = 0; i < 4; i++)
                a[i] = *(const float4*)(Ps + (swz4(ty * 4 + i, k4) << 2));
            #pragma unroll
            for (int jj = 0; jj < 4; jj++)
                bb[jj] = *(const float4*)(Vs + (swz4(k4 * 4 + jj, tx) << 2));
            #pragma unroll
            for (int i = 0; i < 4; i++) {
                acc[i][0] += a[i].x * bb[0].x + a[i].y * bb[1].x + a[i].z * bb[2].x + a[i].w * bb[3].x;
                acc[i][1] += a[i].x * bb[0].y + a[i].y * bb[1].y + a[i].z * bb[2].y + a[i].w * bb[3].y;
                acc[i][2] += a[i].x * bb[0].z + a[i].y * bb[1].z + a[i].z * bb[2].z + a[i].w * bb[3].z;
                acc[i][3] += a[i].x * bb[0].w + a[i].y * bb[1].w + a[i].z * bb[2].w + a[i].w * bb[3].w;
            }
        }
        __syncthreads();
    }

    // Epilogue: write split bf16 (hi | lo | hi) rows of A2' [Mr, 3K]
    __nv_bfloat16* Og = g_A2 + (size_t)(b * Tn + q0) * K3 + h * Dn;
    #pragma unroll
    for (int i = 0; i < 4; i++) {
        const float inv = 1.0f / l_i[i];
        const float v0 = acc[i][0] * inv, v1 = acc[i][1] * inv;
        const float v2 = acc[i][2] * inv, v3 = acc[i][3] * inv;
        __nv_bfloat16 h0, h1, h2, h3, l0, l1, l2, l3;
        split2(v0, h0, l0); split2(v1, h1, l1);
        split2(v2, h2, l2); split2(v3, h3, l3);
        const uint2 hiU = make_uint2(pk2(h0, h1), pk2(h2, h3));
        const uint2 loU = make_uint2(pk2(l0, l1), pk2(l2, l3));
        __nv_bfloat16* p = Og + (size_t)(ty * 4 + i) * K3 + (tx << 2);
        *(uint2*)p          = hiU;
        *(uint2*)(p + 1024) = loU;
        *(uint2*)(p + 2048) = hiU;
    }
}

// ---------------------------------------------------------------------------
// Launch
// ---------------------------------------------------------------------------
extern "C" void kernel_launch(void* const* d_in, const int* in_sizes, int n_in,
                              void* d_out, int out_size)
{
    const float* x      = (const float*)d_in[0];
    const float* W_attn = (const float*)d_in[1];
    const float* b_attn = (const float*)d_in[2];
    const float* W_proj = (const float*)d_in[3];
    const float* b_proj = (const float*)d_in[4];
    float* out = (float*)d_out;

    float *Qp, *Kp, *Vp;
    __nv_bfloat16 *A1p, *B1p, *A2p, *B2p;
    cudaGetSymbolAddress((void**)&Qp, g_Q);
    cudaGetSymbolAddress((void**)&Kp, g_K);
    cudaGetSymbolAddress((void**)&Vp, g_V);
    cudaGetSymbolAddress((void**)&A1p, g_A1);
    cudaGetSymbolAddress((void**)&B1p, g_B1);
    cudaGetSymbolAddress((void**)&A2p, g_A2);
    cudaGetSymbolAddress((void**)&B2p, g_B2);

    // 0) Split/transpose prep
    split_x_kernel<<<(Mr * Cn / 4) / 256, 256>>>(x, A1p);
    tsplit_kernel<<<dim3(Cn / 32, (3 * Cn) / 32), dim3(32, 8)>>>(W_attn, B1p, 3 * Cn);
    tsplit_kernel<<<dim3(Cn / 32, Cn / 32), dim3(32, 8)>>>(W_proj, B2p, Cn);

    // 1) QKV projection (mma.sync), scatter to Q/K/V [B,H,T,D]
    gemm_mma<0><<<dim3((3 * Cn) / 128, Mr / 128), 256>>>(A1p, B1p, b_attn, nullptr);

    // 2) Causal flash attention -> split-bf16 A2'
    {
        const int smem = 4 * 64 * 64 * (int)sizeof(float);
        cudaFuncSetAttribute(flash_kernel,
                             cudaFuncAttributeMaxDynamicSharedMemorySize, smem);
        dim3 grid(Tn / 64, Hn, Bn);
        flash_kernel<<<grid, 256, smem>>>(Qp, Kp, Vp, A2p);
    }

    // 3) Output projection (mma.sync) -> d_out
    gemm_mma<1><<<dim3(Cn / 128, Mr / 128), 256>>>(A2p, B2p, b_proj, out);
}

// round 4
// speedup vs baseline: 2.4744x; 1.6918x over previous
#include <cuda_runtime.h>
#include <cuda_bf16.h>
#include <cstdint>
#include <cstddef>

// Problem constants
constexpr int Bn = 4, Tn = 2048, Cn = 1024, Hn = 16, Dn = 64;
constexpr int Mr = Bn * Tn;      // 8192 rows
constexpr int K3 = 3 * Cn;       // 3072 = split-K (hi|lo|hi)
constexpr int NCH = K3 / 32;     // 96 K-chunks of 32 bf16

// Scratch (device globals — no allocation allowed)
__device__ __nv_bfloat16 g_Qh[(size_t)Bn * Hn * Tn * Dn];
__device__ __nv_bfloat16 g_Ql[(size_t)Bn * Hn * Tn * Dn];
__device__ __nv_bfloat16 g_Kh[(size_t)Bn * Hn * Tn * Dn];
__device__ __nv_bfloat16 g_Kl[(size_t)Bn * Hn * Tn * Dn];
__device__ __nv_bfloat16 g_Vh[(size_t)Bn * Hn * Tn * Dn];
__device__ __nv_bfloat16 g_Vl[(size_t)Bn * Hn * Tn * Dn];
__device__ __nv_bfloat16 g_A1[(size_t)Mr * K3];          // split x
__device__ __nv_bfloat16 g_B1[(size_t)(3 * Cn) * K3];    // split W_attn^T [N,K']
__device__ __nv_bfloat16 g_A2[(size_t)Mr * K3];          // split attn out
__device__ __nv_bfloat16 g_B2[(size_t)Cn * K3];          // split W_proj^T [N,K']

// ---------------------------------------------------------------------------
// Helpers (portable ISA only: mma.sync / ldmatrix / cp.async)
// ---------------------------------------------------------------------------
__device__ __forceinline__ uint32_t smem_u32(const void* p) {
    uint32_t a;
    asm("{ .reg .u64 t; cvta.to.shared.u64 t, %1; cvt.u32.u64 %0, t; }"
        : "=r"(a) : "l"(p));
    return a;
}

__device__ __forceinline__ void cp_async16(uint32_t dst, const void* src) {
    asm volatile("cp.async.cg.shared.global [%0], [%1], 16;"
                 :: "r"(dst), "l"(src) : "memory");
}
__device__ __forceinline__ void cp_commit() {
    asm volatile("cp.async.commit_group;" ::: "memory");
}
__device__ __forceinline__ void cp_wait1() {
    asm volatile("cp.async.wait_group 1;" ::: "memory");
}
__device__ __forceinline__ void cp_wait0() {
    asm volatile("cp.async.wait_group 0;" ::: "memory");
}

__device__ __forceinline__ void ldsm4(uint32_t* r, uint32_t addr) {
    asm volatile("ldmatrix.sync.aligned.m8n8.x4.shared.b16 {%0,%1,%2,%3}, [%4];"
                 : "=r"(r[0]), "=r"(r[1]), "=r"(r[2]), "=r"(r[3]) : "r"(addr));
}
__device__ __forceinline__ void ldsm4t(uint32_t* r, uint32_t addr) {
    asm volatile("ldmatrix.sync.aligned.m8n8.x4.trans.shared.b16 {%0,%1,%2,%3}, [%4];"
                 : "=r"(r[0]), "=r"(r[1]), "=r"(r[2]), "=r"(r[3]) : "r"(addr));
}

__device__ __forceinline__ void mma16816(float* c, const uint32_t* a, const uint32_t* b) {
    asm volatile(
        "mma.sync.aligned.m16n8k16.row.col.f32.bf16.bf16.f32 "
        "{%0,%1,%2,%3}, {%4,%5,%6,%7}, {%8,%9}, {%0,%1,%2,%3};"
        : "+f"(c[0]), "+f"(c[1]), "+f"(c[2]), "+f"(c[3])
        : "r"(a[0]), "r"(a[1]), "r"(a[2]), "r"(a[3]), "r"(b[0]), "r"(b[1]));
}

__device__ __forceinline__ void split2(float v, __nv_bfloat16& h, __nv_bfloat16& l) {
    h = __float2bfloat16_rn(v);
    l = __float2bfloat16_rn(v - __bfloat162float(h));
}
__device__ __forceinline__ uint32_t pk2(__nv_bfloat16 a, __nv_bfloat16 b) {
    __nv_bfloat162 t = __halves2bfloat162(a, b);
    return reinterpret_cast<uint32_t&>(t);
}

// Swizzled byte offset of 16B granule g in row `row` of a [128 x 32]bf16 tile
// (GEMM tiles, 128B lines of 2 rows).
__device__ __forceinline__ uint32_t tswz(int row, int g) {
    const uint32_t line = (uint32_t)(row >> 1);
    const uint32_t gr8  = (uint32_t)(((row & 1) << 2) | g);
    return (line * 8 + (gr8 ^ (line & 7))) * 16;
}

// Flash tiles: [rows][64 bf16] = 128B rows; granule g 0..7 within row.
__device__ __forceinline__ uint32_t fswz(int row, int g) {
    return (uint32_t)(row * 128 + ((g ^ (row & 7)) << 4));
}

// ---------------------------------------------------------------------------
// Prep: split x [Mr, Cn] fp32 -> A' [Mr, 3K] bf16  (hi | lo | hi)
// ---------------------------------------------------------------------------
__global__ void split_x_kernel(const float* __restrict__ x, __nv_bfloat16* __restrict__ A)
{
    const size_t gid = (size_t)blockIdx.x * 256 + threadIdx.x;
    const size_t f = gid * 4;
    const int m = (int)(f >> 10);
    const int c = (int)(f & 1023);
    const float4 v = *(const float4*)(x + f);
    __nv_bfloat16 h0, h1, h2, h3, l0, l1, l2, l3;
    split2(v.x, h0, l0); split2(v.y, h1, l1);
    split2(v.z, h2, l2); split2(v.w, h3, l3);
    uint2 hiU = make_uint2(pk2(h0, h1), pk2(h2, h3));
    uint2 loU = make_uint2(pk2(l0, l1), pk2(l2, l3));
    __nv_bfloat16* p = A + (size_t)m * K3 + c;
    *(uint2*)p          = hiU;
    *(uint2*)(p + 1024) = loU;
    *(uint2*)(p + 2048) = hiU;
}

// ---------------------------------------------------------------------------
// Prep: transpose-split W [K=1024, N] fp32 -> B' [N, 3K] bf16  (hi | hi | lo)
// ---------------------------------------------------------------------------
__global__ void tsplit_kernel(const float* __restrict__ W, __nv_bfloat16* __restrict__ Bp, int N)
{
    __shared__ float sm[32][33];
    const int k0 = blockIdx.x * 32, n0 = blockIdx.y * 32;
    const int tx = threadIdx.x, ty = threadIdx.y;
    #pragma unroll
    for (int r = 0; r < 4; r++)
        sm[ty + r * 8][tx] = W[(size_t)(k0 + ty + r * 8) * N + n0 + tx];
    __syncthreads();
    #pragma unroll
    for (int r = 0; r < 4; r++) {
        const int n = n0 + ty + r * 8, k = k0 + tx;
        const float v = sm[tx][ty + r * 8];
        __nv_bfloat16 h, l; split2(v, h, l);
        __nv_bfloat16* p = Bp + (size_t)n * K3 + k;
        p[0] = h; p[1024] = h; p[2048] = l;
    }
}

// ---------------------------------------------------------------------------
// mma.sync GEMM (unchanged structure). MODE 0: epilogue splits into
// Qh/Ql/Kh/Kl/Vh/Vl bf16. MODE 1: fp32 out.
// ---------------------------------------------------------------------------
template <int MODE>
__global__ __launch_bounds__(256, 2)
void gemm_mma(const __nv_bfloat16* __restrict__ A, const __nv_bfloat16* __restrict__ Bm,
              const float* __restrict__ bias, float* __restrict__ Cout)
{
    __shared__ __align__(1024) char smem[3 * 16384];
    const uint32_t sb = smem_u32(smem);

    const int tid  = threadIdx.x;
    const int lane = tid & 31;
    const int w    = tid >> 5;
    const int wm   = (w & 1) * 64;
    const int wn   = (w >> 1) * 32;
    const int bm   = blockIdx.y << 7;
    const int bn   = blockIdx.x << 7;

    const int lrow = tid >> 1;
    const int lg   = (tid & 1) << 1;
    const __nv_bfloat16* gA = A  + (size_t)(bm + lrow) * K3 + lg * 8;
    const __nv_bfloat16* gB = Bm + (size_t)(bn + lrow) * K3 + lg * 8;
    const uint32_t dA0 = tswz(lrow, lg), dA1 = tswz(lrow, lg + 1);

    auto load_stage = [&](int stage, int ic) {
        const uint32_t aBase = sb + stage * 16384;
        const uint32_t bBase = aBase + 8192;
        const int koff = ic * 32;
        cp_async16(aBase + dA0, gA + koff);
        cp_async16(aBase + dA1, gA + koff + 8);
        cp_async16(bBase + dA0, gB + koff);
        cp_async16(bBase + dA1, gB + koff + 8);
    };

    float acc[4][4][4];
    #pragma unroll
    for (int i = 0; i < 4; i++)
        #pragma unroll
        for (int j = 0; j < 4; j++)
            #pragma unroll
            for (int r = 0; r < 4; r++) acc[i][j][r] = 0.0f;

    load_stage(0, 0); cp_commit();
    load_stage(1, 1); cp_commit();

    const int aRow = (lane & 15);
    const int aG   = (lane >> 4);
    const int bRow = (lane & 7) + ((lane >> 4) << 3);
    const int bG   = ((lane >> 3) & 1);

    for (int ic = 0; ic < NCH; ic++) {
        const int s = ic % 3;
        cp_wait1();
        __syncthreads();
        if (ic + 2 < NCH) load_stage((ic + 2) % 3, ic + 2);
        cp_commit();

        const uint32_t aBase = sb + s * 16384;
        const uint32_t bBase = aBase + 8192;

        #pragma unroll
        for (int ks = 0; ks < 2; ks++) {
            uint32_t af[4][4], bf[2][4];
            #pragma unroll
            for (int tm = 0; tm < 4; tm++)
                ldsm4(af[tm], aBase + tswz(wm + tm * 16 + aRow, ks * 2 + aG));
            #pragma unroll
            for (int tp = 0; tp < 2; tp++)
                ldsm4(bf[tp], bBase + tswz(wn + tp * 16 + bRow, ks * 2 + bG));
            #pragma unroll
            for (int tm = 0; tm < 4; tm++)
                #pragma unroll
                for (int tn = 0; tn < 4; tn++)
                    mma16816(acc[tm][tn], af[tm], &bf[tn >> 1][(tn & 1) * 2]);
        }
        __syncthreads();
    }

    const int gq = lane >> 2;
    const int t4 = lane & 3;
    #pragma unroll
    for (int tm = 0; tm < 4; tm++) {
        #pragma unroll
        for (int tn = 0; tn < 4; tn++) {
            const int n = bn + wn + tn * 8 + t4 * 2;
            const float2 bv = *(const float2*)(bias + n);
            #pragma unroll
            for (int half = 0; half < 2; half++) {
                const int m = bm + wm + tm * 16 + gq + half * 8;
                float2 o;
                o.x = acc[tm][tn][half * 2 + 0] + bv.x;
                o.y = acc[tm][tn][half * 2 + 1] + bv.y;
                if (MODE == 1) {
                    *(float2*)(Cout + (size_t)m * Cn + n) = o;
                } else {
                    const int part = n >> 10, c = n & 1023, hh = c >> 6, d = c & 63;
                    const int b2 = m >> 11, t = m & 2047;
                    const size_t idx = ((size_t)((b2 * Hn + hh) * Tn + t)) * 64 + d;
                    __nv_bfloat16 h0, l0, h1, l1;
                    split2(o.x, h0, l0); split2(o.y, h1, l1);
                    const uint32_t hiw = pk2(h0, h1), low = pk2(l0, l1);
                    if (part == 0) {
                        *(uint32_t*)(g_Qh + idx) = hiw; *(uint32_t*)(g_Ql + idx) = low;
                    } else if (part == 1) {
                        *(uint32_t*)(g_Kh + idx) = hiw; *(uint32_t*)(g_Kl + idx) = low;
                    } else {
                        *(uint32_t*)(g_Vh + idx) = hiw; *(uint32_t*)(g_Vl + idx) = low;
                    }
                }
            }
        }
    }
}

// ---------------------------------------------------------------------------
// Tensorized flash attention (causal). CTA = 128 q-rows, 8 warps x 16 rows,
// full 64-key width per warp. Split-bf16 3-product for S and PV.
// Epilogue writes split-bf16 A2' (hi|lo|hi).
// ---------------------------------------------------------------------------
__global__ __launch_bounds__(256, 1)
void flash2(const __nv_bfloat16* __restrict__ Qh, const __nv_bfloat16* __restrict__ Ql,
            const __nv_bfloat16* __restrict__ Kh, const __nv_bfloat16* __restrict__ Kl,
            const __nv_bfloat16* __restrict__ Vh, const __nv_bfloat16* __restrict__ Vl,
            __nv_bfloat16* __restrict__ Out)
{
    extern __shared__ char sm2[];
    const uint32_t sb = smem_u32(sm2);

    const int tid = threadIdx.x, lane = tid & 31, w = tid >> 5;
    const int bx = blockIdx.x, h = blockIdx.y, b = blockIdx.z;
    const int q0 = bx << 7;
    const int wm = w << 4;
    const size_t hoff = (size_t)((b * Hn + h) * Tn) * 64;
    const int nkt = 2 * bx + 2;

    // Load Q tiles (Qh -> [0,16K), Ql -> [16K,32K))
    {
        const int r = tid >> 1;
        const int gbase = (tid & 1) * 4;
        const __nv_bfloat16* qhp = Qh + hoff + (size_t)(q0 + r) * 64;
        const __nv_bfloat16* qlp = Ql + hoff + (size_t)(q0 + r) * 64;
        #pragma unroll
        for (int i = 0; i < 4; i++) {
            const int g = gbase + i;
            const uint32_t off = fswz(r, g);
            *(uint4*)(sm2 + off)         = *(const uint4*)(qhp + g * 8);
            *(uint4*)(sm2 + 16384 + off) = *(const uint4*)(qlp + g * 8);
        }
    }
    __syncthreads();

    // Q A-fragments (per warp, all of k=64 over 4 k16 chunks)
    uint32_t qhf[4][4], qlf[4][4];
    {
        const int row = wm + (lane & 7) + (((lane >> 3) & 1) << 3);
        #pragma unroll
        for (int kc = 0; kc < 4; kc++) {
            const int g = 2 * kc + (lane >> 4);
            const uint32_t off = fswz(row, g);
            ldsm4(qhf[kc], sb + off);
            ldsm4(qlf[kc], sb + 16384 + off);
        }
    }

    // K/V pipeline: stage s at 32768 + s*32768: Kh, Kl, Vh, Vl (8KB each)
    const int lr = tid & 63, lg0 = (tid >> 6) << 1;
    auto load_kv = [&](int stage, int kt) {
        const uint32_t base = sb + 32768 + stage * 32768;
        const size_t src = hoff + (size_t)(kt * 64 + lr) * 64 + lg0 * 8;
        const uint32_t o0 = fswz(lr, lg0), o1 = fswz(lr, lg0 + 1);
        cp_async16(base + o0,         Kh + src);
        cp_async16(base + o1,         Kh + src + 8);
        cp_async16(base + 8192 + o0,  Kl + src);
        cp_async16(base + 8192 + o1,  Kl + src + 8);
        cp_async16(base + 16384 + o0, Vh + src);
        cp_async16(base + 16384 + o1, Vh + src + 8);
        cp_async16(base + 24576 + o0, Vl + src);
        cp_async16(base + 24576 + o1, Vl + src + 8);
    };
    load_kv(0, 0); cp_commit();
    load_kv(1, 1); cp_commit();

    float oacc[8][4];
    #pragma unroll
    for (int j = 0; j < 8; j++)
        #pragma unroll
        for (int r = 0; r < 4; r++) oacc[j][r] = 0.0f;
    float m0 = -1e30f, m8 = -1e30f, l0 = 0.0f, l8 = 0.0f;

    const int qr0 = q0 + wm + (lane >> 2);

    for (int kt = 0; kt < nkt; kt++) {
        if (kt == nkt - 1) cp_wait0(); else cp_wait1();
        __syncthreads();
        const uint32_t base = sb + 32768 + (kt & 1) * 32768;
        const bool active = (kt * 64 <= q0 + wm + 15);
        if (active) {
            // ---- S = Q K^T (3-term split) ----
            float sacc[8][4];
            #pragma unroll
            for (int j = 0; j < 8; j++)
                #pragma unroll
                for (int r = 0; r < 4; r++) sacc[j][r] = 0.0f;

            const int krow0 = (lane & 7) + ((lane >> 4) << 3);
            const int kgsel = (lane >> 3) & 1;
            #pragma unroll
            for (int kc = 0; kc < 4; kc++) {
                #pragma unroll
                for (int p = 0; p < 4; p++) {
                    const int row = p * 16 + krow0;
                    const uint32_t off = fswz(row, 2 * kc + kgsel);
                    uint32_t bh[4], bl[4];
                    ldsm4(bh, base + off);
                    ldsm4(bl, base + 8192 + off);
                    mma16816(sacc[2 * p],     qhf[kc], bh);
                    mma16816(sacc[2 * p + 1], qhf[kc], bh + 2);
                    mma16816(sacc[2 * p],     qlf[kc], bh);
                    mma16816(sacc[2 * p + 1], qlf[kc], bh + 2);
                    mma16816(sacc[2 * p],     qhf[kc], bl);
                    mma16816(sacc[2 * p + 1], qhf[kc], bl + 2);
                }
            }

            // ---- softmax ----
            const bool maskw = (kt * 64 + 63 > q0 + wm);
            float rmax0 = -1e30f, rmax8 = -1e30f;
            #pragma unroll
            for (int j = 0; j < 8; j++) {
                sacc[j][0] *= 0.125f; sacc[j][1] *= 0.125f;
                sacc[j][2] *= 0.125f; sacc[j][3] *= 0.125f;
                if (maskw) {
                    const int col = kt * 64 + j * 8 + ((lane & 3) << 1);
                    if (col     > qr0)     sacc[j][0] = -1e30f;
                    if (col + 1 > qr0)     sacc[j][1] = -1e30f;
                    if (col     > qr0 + 8) sacc[j][2] = -1e30f;
                    if (col + 1 > qr0 + 8) sacc[j][3] = -1e30f;
                }
                rmax0 = fmaxf(rmax0, fmaxf(sacc[j][0], sacc[j][1]));
                rmax8 = fmaxf(rmax8, fmaxf(sacc[j][2], sacc[j][3]));
            }
            rmax0 = fmaxf(rmax0, __shfl_xor_sync(0xffffffffu, rmax0, 1));
            rmax0 = fmaxf(rmax0, __shfl_xor_sync(0xffffffffu, rmax0, 2));
            rmax8 = fmaxf(rmax8, __shfl_xor_sync(0xffffffffu, rmax8, 1));
            rmax8 = fmaxf(rmax8, __shfl_xor_sync(0xffffffffu, rmax8, 2));

            const float mn0 = fmaxf(m0, rmax0), mn8 = fmaxf(m8, rmax8);
            const float a0 = __expf(m0 - mn0), a8 = __expf(m8 - mn8);
            m0 = mn0; m8 = mn8;

            float rs0 = 0.0f, rs8 = 0.0f;
            uint32_t ph[8][2], pl[8][2];
            #pragma unroll
            for (int j = 0; j < 8; j++) {
                const float p0 = __expf(sacc[j][0] - m0);
                const float p1 = __expf(sacc[j][1] - m0);
                const float p2 = __expf(sacc[j][2] - m8);
                const float p3 = __expf(sacc[j][3] - m8);
                rs0 += p0 + p1; rs8 += p2 + p3;
                __nv_bfloat16 b0, b1, b2, b3, r0b, r1b, r2b, r3b;
                split2(p0, b0, r0b); split2(p1, b1, r1b);
                split2(p2, b2, r2b); split2(p3, b3, r3b);
                ph[j][0] = pk2(b0, b1);  ph[j][1] = pk2(b2, b3);
                pl[j][0] = pk2(r0b, r1b); pl[j][1] = pk2(r2b, r3b);
            }
            rs0 += __shfl_xor_sync(0xffffffffu, rs0, 1);
            rs0 += __shfl_xor_sync(0xffffffffu, rs0, 2);
            rs8 += __shfl_xor_sync(0xffffffffu, rs8, 1);
            rs8 += __shfl_xor_sync(0xffffffffu, rs8, 2);
            l0 = l0 * a0 + rs0;
            l8 = l8 * a8 + rs8;

            #pragma unroll
            for (int j = 0; j < 8; j++) {
                oacc[j][0] *= a0; oacc[j][1] *= a0;
                oacc[j][2] *= a8; oacc[j][3] *= a8;
            }

            // ---- O += P V (3-term split) ----
            const int vrow0 = (lane & 7) + (((lane >> 3) & 1) << 3);
            const int vgsel = lane >> 4;
            #pragma unroll
            for (int kc = 0; kc < 4; kc++) {
                const uint32_t ah[4] = { ph[2 * kc][0], ph[2 * kc][1],
                                         ph[2 * kc + 1][0], ph[2 * kc + 1][1] };
                const uint32_t al[4] = { pl[2 * kc][0], pl[2 * kc][1],
                                         pl[2 * kc + 1][0], pl[2 * kc + 1][1] };
                const int row = kc * 16 + vrow0;
                #pragma unroll
                for (int gd = 0; gd < 4; gd++) {
                    const uint32_t off = fswz(row, 2 * gd + vgsel);
                    uint32_t vh[4], vl[4];
                    ldsm4t(vh, base + 16384 + off);
                    ldsm4t(vl, base + 24576 + off);
                    mma16816(oacc[2 * gd],     ah, vh);
                    mma16816(oacc[2 * gd + 1], ah, vh + 2);
                    mma16816(oacc[2 * gd],     al, vh);
                    mma16816(oacc[2 * gd + 1], al, vh + 2);
                    mma16816(oacc[2 * gd],     ah, vl);
                    mma16816(oacc[2 * gd + 1], ah, vl + 2);
                }
            }
        }
        __syncthreads();
        if (kt + 2 < nkt) { load_kv(kt & 1, kt + 2); cp_commit(); }
    }

    // ---- epilogue: normalize + write split-bf16 A2' (hi|lo|hi) ----
    const float inv0 = 1.0f / l0, inv8 = 1.0f / l8;
    const int row0 = q0 + wm + (lane >> 2);
    __nv_bfloat16* o0p = Out + (size_t)(b * Tn + row0) * K3 + h * 64 + ((lane & 3) << 1);
    __nv_bfloat16* o8p = o0p + (size_t)8 * K3;
    #pragma unroll
    for (int j = 0; j < 8; j++) {
        {
            const float v0 = oacc[j][0] * inv0, v1 = oacc[j][1] * inv0;
            __nv_bfloat16 h0, l0b, h1, l1b;
            split2(v0, h0, l0b); split2(v1, h1, l1b);
            *(uint32_t*)(o0p + j * 8)        = pk2(h0, h1);
            *(uint32_t*)(o0p + j * 8 + 1024) = pk2(l0b, l1b);
            *(uint32_t*)(o0p + j * 8 + 2048) = pk2(h0, h1);
        }
        {
            const float v0 = oacc[j][2] * inv8, v1 = oacc[j][3] * inv8;
            __nv_bfloat16 h0, l0b, h1, l1b;
            split2(v0, h0, l0b); split2(v1, h1, l1b);
            *(uint32_t*)(o8p + j * 8)        = pk2(h0, h1);
            *(uint32_t*)(o8p + j * 8 + 1024) = pk2(l0b, l1b);
            *(uint32_t*)(o8p + j * 8 + 2048) = pk2(h0, h1);
        }
    }
}

// ---------------------------------------------------------------------------
// Launch
// ---------------------------------------------------------------------------
extern "C" void kernel_launch(void* const* d_in, const int* in_sizes, int n_in,
                              void* d_out, int out_size)
{
    const float* x      = (const float*)d_in[0];
    const float* W_attn = (const float*)d_in[1];
    const float* b_attn = (const float*)d_in[2];
    const float* W_proj = (const float*)d_in[3];
    const float* b_proj = (const float*)d_in[4];
    float* out = (float*)d_out;

    __nv_bfloat16 *A1p, *B1p, *A2p, *B2p;
    __nv_bfloat16 *Qhp, *Qlp, *Khp, *Klp, *Vhp, *Vlp;
    cudaGetSymbolAddress((void**)&A1p, g_A1);
    cudaGetSymbolAddress((void**)&B1p, g_B1);
    cudaGetSymbolAddress((void**)&A2p, g_A2);
    cudaGetSymbolAddress((void**)&B2p, g_B2);
    cudaGetSymbolAddress((void**)&Qhp, g_Qh);
    cudaGetSymbolAddress((void**)&Qlp, g_Ql);
    cudaGetSymbolAddress((void**)&Khp, g_Kh);
    cudaGetSymbolAddress((void**)&Klp, g_Kl);
    cudaGetSymbolAddress((void**)&Vhp, g_Vh);
    cudaGetSymbolAddress((void**)&Vlp, g_Vl);

    // 0) Split/transpose prep
    split_x_kernel<<<(Mr * Cn / 4) / 256, 256>>>(x, A1p);
    tsplit_kernel<<<dim3(Cn / 32, (3 * Cn) / 32), dim3(32, 8)>>>(W_attn, B1p, 3 * Cn);
    tsplit_kernel<<<dim3(Cn / 32, Cn / 32), dim3(32, 8)>>>(W_proj, B2p, Cn);

    // 1) QKV projection (mma.sync), split-bf16 scatter to Qh/Ql/Kh/Kl/Vh/Vl
    gemm_mma<0><<<dim3((3 * Cn) / 128, Mr / 128), 256>>>(A1p, B1p, b_attn, nullptr);

    // 2) Tensorized causal flash attention -> split-bf16 A2'
    {
        const int smem = 32768 + 2 * 32768;   // Q tiles + 2 KV stages = 96KB
        cudaFuncSetAttribute(flash2, cudaFuncAttributeMaxDynamicSharedMemorySize, smem);
        dim3 grid(Tn / 128, Hn, Bn);
        flash2<<<grid, 256, smem>>>(Qhp, Qlp, Khp, Klp, Vhp, Vlp, A2p);
    }

    // 3) Output projection (mma.sync) -> d_out
    gemm_mma<1><<<dim3(Cn / 128, Mr / 128), 256>>>(A2p, B2p, b_proj, out);
}

// round 5
// speedup vs baseline: 2.4807x; 1.0026x over previous
#include <cuda_runtime.h>
#include <cuda_bf16.h>
#include <cstdint>
#include <cstddef>

// Problem constants
constexpr int Bn = 4, Tn = 2048, Cn = 1024, Hn = 16, Dn = 64;
constexpr int Mr = Bn * Tn;      // 8192 rows
constexpr int K3 = 3 * Cn;       // 3072 = split-K (hi|lo|hi)
constexpr int NCH = K3 / 32;     // 96 K-chunks of 32 bf16

// Scratch (device globals — no allocation allowed)
__device__ __nv_bfloat16 g_Qh[(size_t)Bn * Hn * Tn * Dn];
__device__ __nv_bfloat16 g_Ql[(size_t)Bn * Hn * Tn * Dn];
__device__ __nv_bfloat16 g_Kh[(size_t)Bn * Hn * Tn * Dn];
__device__ __nv_bfloat16 g_Kl[(size_t)Bn * Hn * Tn * Dn];
__device__ __nv_bfloat16 g_Vh[(size_t)Bn * Hn * Tn * Dn];
__device__ __nv_bfloat16 g_Vl[(size_t)Bn * Hn * Tn * Dn];
__device__ __nv_bfloat16 g_A1[(size_t)Mr * K3];          // split x
__device__ __nv_bfloat16 g_B1[(size_t)(3 * Cn) * K3];    // split W_attn^T [N,K']
__device__ __nv_bfloat16 g_A2[(size_t)Mr * K3];          // split attn out
__device__ __nv_bfloat16 g_B2[(size_t)Cn * K3];          // split W_proj^T [N,K']

// ---------------------------------------------------------------------------
// Helpers (portable ISA only: mma.sync / ldmatrix / cp.async)
// ---------------------------------------------------------------------------
__device__ __forceinline__ uint32_t smem_u32(const void* p) {
    uint32_t a;
    asm("{ .reg .u64 t; cvta.to.shared.u64 t, %1; cvt.u32.u64 %0, t; }"
        : "=r"(a) : "l"(p));
    return a;
}

__device__ __forceinline__ void cp_async16(uint32_t dst, const void* src) {
    asm volatile("cp.async.cg.shared.global [%0], [%1], 16;"
                 :: "r"(dst), "l"(src) : "memory");
}
__device__ __forceinline__ void cp_commit() {
    asm volatile("cp.async.commit_group;" ::: "memory");
}
__device__ __forceinline__ void cp_wait2() {
    asm volatile("cp.async.wait_group 2;" ::: "memory");
}

__device__ __forceinline__ void ldsm4(uint32_t* r, uint32_t addr) {
    asm volatile("ldmatrix.sync.aligned.m8n8.x4.shared.b16 {%0,%1,%2,%3}, [%4];"
                 : "=r"(r[0]), "=r"(r[1]), "=r"(r[2]), "=r"(r[3]) : "r"(addr));
}
__device__ __forceinline__ void ldsm4t(uint32_t* r, uint32_t addr) {
    asm volatile("ldmatrix.sync.aligned.m8n8.x4.trans.shared.b16 {%0,%1,%2,%3}, [%4];"
                 : "=r"(r[0]), "=r"(r[1]), "=r"(r[2]), "=r"(r[3]) : "r"(addr));
}

__device__ __forceinline__ void mma16816(float* c, const uint32_t* a, const uint32_t* b) {
    asm volatile(
        "mma.sync.aligned.m16n8k16.row.col.f32.bf16.bf16.f32 "
        "{%0,%1,%2,%3}, {%4,%5,%6,%7}, {%8,%9}, {%0,%1,%2,%3};"
        : "+f"(c[0]), "+f"(c[1]), "+f"(c[2]), "+f"(c[3])
        : "r"(a[0]), "r"(a[1]), "r"(a[2]), "r"(a[3]), "r"(b[0]), "r"(b[1]));
}

__device__ __forceinline__ void split2(float v, __nv_bfloat16& h, __nv_bfloat16& l) {
    h = __float2bfloat16_rn(v);
    l = __float2bfloat16_rn(v - __bfloat162float(h));
}
__device__ __forceinline__ uint32_t pk2(__nv_bfloat16 a, __nv_bfloat16 b) {
    __nv_bfloat162 t = __halves2bfloat162(a, b);
    return reinterpret_cast<uint32_t&>(t);
}

// Swizzled byte offset of 16B granule g in row `row` of a [128 x 32]bf16 tile
// (GEMM tiles, 128B lines of 2 rows).
__device__ __forceinline__ uint32_t tswz(int row, int g) {
    const uint32_t line = (uint32_t)(row >> 1);
    const uint32_t gr8  = (uint32_t)(((row & 1) << 2) | g);
    return (line * 8 + (gr8 ^ (line & 7))) * 16;
}

// Flash tiles: [rows][64 bf16] = 128B rows; granule g 0..7 within row.
__device__ __forceinline__ uint32_t fswz(int row, int g) {
    return (uint32_t)(row * 128 + ((g ^ (row & 7)) << 4));
}

// ---------------------------------------------------------------------------
// Prep: split x [Mr, Cn] fp32 -> A' [Mr, 3K] bf16  (hi | lo | hi)
// ---------------------------------------------------------------------------
__global__ void split_x_kernel(const float* __restrict__ x, __nv_bfloat16* __restrict__ A)
{
    const size_t gid = (size_t)blockIdx.x * 256 + threadIdx.x;
    const size_t f = gid * 4;
    const int m = (int)(f >> 10);
    const int c = (int)(f & 1023);
    const float4 v = *(const float4*)(x + f);
    __nv_bfloat16 h0, h1, h2, h3, l0, l1, l2, l3;
    split2(v.x, h0, l0); split2(v.y, h1, l1);
    split2(v.z, h2, l2); split2(v.w, h3, l3);
    uint2 hiU = make_uint2(pk2(h0, h1), pk2(h2, h3));
    uint2 loU = make_uint2(pk2(l0, l1), pk2(l2, l3));
    __nv_bfloat16* p = A + (size_t)m * K3 + c;
    *(uint2*)p          = hiU;
    *(uint2*)(p + 1024) = loU;
    *(uint2*)(p + 2048) = hiU;
}

// ---------------------------------------------------------------------------
// Prep: transpose-split W [K=1024, N] fp32 -> B' [N, 3K] bf16  (hi | hi | lo)
// ---------------------------------------------------------------------------
__global__ void tsplit_kernel(const float* __restrict__ W, __nv_bfloat16* __restrict__ Bp, int N)
{
    __shared__ float sm[32][33];
    const int k0 = blockIdx.x * 32, n0 = blockIdx.y * 32;
    const int tx = threadIdx.x, ty = threadIdx.y;
    #pragma unroll
    for (int r = 0; r < 4; r++)
        sm[ty + r * 8][tx] = W[(size_t)(k0 + ty + r * 8) * N + n0 + tx];
    __syncthreads();
    #pragma unroll
    for (int r = 0; r < 4; r++) {
        const int n = n0 + ty + r * 8, k = k0 + tx;
        const float v = sm[tx][ty + r * 8];
        __nv_bfloat16 h, l; split2(v, h, l);
        __nv_bfloat16* p = Bp + (size_t)n * K3 + k;
        p[0] = h; p[1024] = h; p[2048] = l;
    }
}

// ---------------------------------------------------------------------------
// mma.sync GEMM. 128x128 CTA, BK=32, 8 warps (2x4), warp tile 64x32,
// 4-stage cp.async pipeline, ONE __syncthreads per iteration.
// MODE 0: epilogue splits into Qh/Ql/Kh/Kl/Vh/Vl. MODE 1: fp32 out.
// ---------------------------------------------------------------------------
template <int MODE>
__global__ __launch_bounds__(256, 2)
void gemm_mma(const __nv_bfloat16* __restrict__ A, const __nv_bfloat16* __restrict__ Bm,
              const float* __restrict__ bias, float* __restrict__ Cout)
{
    extern __shared__ __align__(1024) char smem[];   // 4 stages x 16KB
    const uint32_t sb = smem_u32(smem);

    const int tid  = threadIdx.x;
    const int lane = tid & 31;
    const int w    = tid >> 5;
    const int wm   = (w & 1) * 64;
    const int wn   = (w >> 1) * 32;
    const int bm   = blockIdx.y << 7;
    const int bn   = blockIdx.x << 7;

    const int lrow = tid >> 1;
    const int lg   = (tid & 1) << 1;
    const __nv_bfloat16* gA = A  + (size_t)(bm + lrow) * K3 + lg * 8;
    const __nv_bfloat16* gB = Bm + (size_t)(bn + lrow) * K3 + lg * 8;
    const uint32_t dA0 = tswz(lrow, lg), dA1 = tswz(lrow, lg + 1);

    auto load_stage = [&](int stage, int ic) {
        const uint32_t aBase = sb + stage * 16384;
        const uint32_t bBase = aBase + 8192;
        const int koff = ic * 32;
        cp_async16(aBase + dA0, gA + koff);
        cp_async16(aBase + dA1, gA + koff + 8);
        cp_async16(bBase + dA0, gB + koff);
        cp_async16(bBase + dA1, gB + koff + 8);
    };

    float acc[4][4][4];
    #pragma unroll
    for (int i = 0; i < 4; i++)
        #pragma unroll
        for (int j = 0; j < 4; j++)
            #pragma unroll
            for (int r = 0; r < 4; r++) acc[i][j][r] = 0.0f;

    load_stage(0, 0); cp_commit();
    load_stage(1, 1); cp_commit();
    load_stage(2, 2); cp_commit();

    const int aRow = (lane & 15);
    const int aG   = (lane >> 4);
    const int bRow = (lane & 7) + ((lane >> 4) << 3);
    const int bG   = ((lane >> 3) & 1);

    for (int ic = 0; ic < NCH; ic++) {
        const int s = ic & 3;
        cp_wait2();                  // stage ic complete (2 newer groups may pend)
        __syncthreads();             // all warps done with stage (ic+3)&3 reads
        if (ic + 3 < NCH) load_stage((ic + 3) & 3, ic + 3);
        cp_commit();

        const uint32_t aBase = sb + s * 16384;
        const uint32_t bBase = aBase + 8192;

        #pragma unroll
        for (int ks = 0; ks < 2; ks++) {
            uint32_t af[4][4], bf[2][4];
            #pragma unroll
            for (int tm = 0; tm < 4; tm++)
                ldsm4(af[tm], aBase + tswz(wm + tm * 16 + aRow, ks * 2 + aG));
            #pragma unroll
            for (int tp = 0; tp < 2; tp++)
                ldsm4(bf[tp], bBase + tswz(wn + tp * 16 + bRow, ks * 2 + bG));
            #pragma unroll
            for (int tm = 0; tm < 4; tm++)
                #pragma unroll
                for (int tn = 0; tn < 4; tn++)
                    mma16816(acc[tm][tn], af[tm], &bf[tn >> 1][(tn & 1) * 2]);
        }
    }

    __syncthreads();

    const int gq = lane >> 2;
    const int t4 = lane & 3;
    #pragma unroll
    for (int tm = 0; tm < 4; tm++) {
        #pragma unroll
        for (int tn = 0; tn < 4; tn++) {
            const int n = bn + wn + tn * 8 + t4 * 2;
            const float2 bv = *(const float2*)(bias + n);
            #pragma unroll
            for (int half = 0; half < 2; half++) {
                const int m = bm + wm + tm * 16 + gq + half * 8;
                float2 o;
                o.x = acc[tm][tn][half * 2 + 0] + bv.x;
                o.y = acc[tm][tn][half * 2 + 1] + bv.y;
                if (MODE == 1) {
                    *(float2*)(Cout + (size_t)m * Cn + n) = o;
                } else {
                    const int part = n >> 10, c = n & 1023, hh = c >> 6, d = c & 63;
                    const int b2 = m >> 11, t = m & 2047;
                    const size_t idx = ((size_t)((b2 * Hn + hh) * Tn + t)) * 64 + d;
                    __nv_bfloat16 h0, l0, h1, l1;
                    split2(o.x, h0, l0); split2(o.y, h1, l1);
                    const uint32_t hiw = pk2(h0, h1), low = pk2(l0, l1);
                    if (part == 0) {
                        *(uint32_t*)(g_Qh + idx) = hiw; *(uint32_t*)(g_Ql + idx) = low;
                    } else if (part == 1) {
                        *(uint32_t*)(g_Kh + idx) = hiw; *(uint32_t*)(g_Kl + idx) = low;
                    } else {
                        *(uint32_t*)(g_Vh + idx) = hiw; *(uint32_t*)(g_Vl + idx) = low;
                    }
                }
            }
        }
    }
}

// ---------------------------------------------------------------------------
// Tensorized flash attention (causal). CTA = 128 q-rows, 8 warps x 16 rows,
// full 64-key width per warp. Split-bf16 3-product for S and PV.
// 4-stage KV pipeline, one __syncthreads per K-tile.
// ---------------------------------------------------------------------------
__global__ __launch_bounds__(256, 1)
void flash2(const __nv_bfloat16* __restrict__ Qh, const __nv_bfloat16* __restrict__ Ql,
            const __nv_bfloat16* __restrict__ Kh, const __nv_bfloat16* __restrict__ Kl,
            const __nv_bfloat16* __restrict__ Vh, const __nv_bfloat16* __restrict__ Vl,
            __nv_bfloat16* __restrict__ Out)
{
    extern __shared__ char sm2[];
    const uint32_t sb = smem_u32(sm2);

    const int tid = threadIdx.x, lane = tid & 31, w = tid >> 5;
    const int bx = blockIdx.x, h = blockIdx.y, b = blockIdx.z;
    const int q0 = bx << 7;
    const int wm = w << 4;
    const size_t hoff = (size_t)((b * Hn + h) * Tn) * 64;
    const int nkt = 2 * bx + 2;

    // Load Q tiles (Qh -> [0,16K), Ql -> [16K,32K))
    {
        const int r = tid >> 1;
        const int gbase = (tid & 1) * 4;
        const __nv_bfloat16* qhp = Qh + hoff + (size_t)(q0 + r) * 64;
        const __nv_bfloat16* qlp = Ql + hoff + (size_t)(q0 + r) * 64;
        #pragma unroll
        for (int i = 0; i < 4; i++) {
            const int g = gbase + i;
            const uint32_t off = fswz(r, g);
            *(uint4*)(sm2 + off)         = *(const uint4*)(qhp + g * 8);
            *(uint4*)(sm2 + 16384 + off) = *(const uint4*)(qlp + g * 8);
        }
    }

    // K/V pipeline: stage s at 32768 + s*32768: Kh, Kl, Vh, Vl (8KB each)
    const int lr = tid & 63, lg0 = (tid >> 6) << 1;
    auto load_kv = [&](int stage, int kt) {
        const uint32_t base = sb + 32768 + stage * 32768;
        const size_t src = hoff + (size_t)(kt * 64 + lr) * 64 + lg0 * 8;
        const uint32_t o0 = fswz(lr, lg0), o1 = fswz(lr, lg0 + 1);
        cp_async16(base + o0,         Kh + src);
        cp_async16(base + o1,         Kh + src + 8);
        cp_async16(base + 8192 + o0,  Kl + src);
        cp_async16(base + 8192 + o1,  Kl + src + 8);
        cp_async16(base + 16384 + o0, Vh + src);
        cp_async16(base + 16384 + o1, Vh + src + 8);
        cp_async16(base + 24576 + o0, Vl + src);
        cp_async16(base + 24576 + o1, Vl + src + 8);
    };
    load_kv(0, 0); cp_commit();
    if (1 < nkt) load_kv(1, 1);
    cp_commit();
    if (2 < nkt) load_kv(2, 2);
    cp_commit();

    __syncthreads();   // Q tiles visible

    // Q A-fragments (per warp, all of k=64 over 4 k16 chunks)
    uint32_t qhf[4][4], qlf[4][4];
    {
        const int row = wm + (lane & 7) + (((lane >> 3) & 1) << 3);
        #pragma unroll
        for (int kc = 0; kc < 4; kc++) {
            const int g = 2 * kc + (lane >> 4);
            const uint32_t off = fswz(row, g);
            ldsm4(qhf[kc], sb + off);
            ldsm4(qlf[kc], sb + 16384 + off);
        }
    }

    float oacc[8][4];
    #pragma unroll
    for (int j = 0; j < 8; j++)
        #pragma unroll
        for (int r = 0; r < 4; r++) oacc[j][r] = 0.0f;
    float m0 = -1e30f, m8 = -1e30f, l0 = 0.0f, l8 = 0.0f;

    const int qr0 = q0 + wm + (lane >> 2);

    for (int kt = 0; kt < nkt; kt++) {
        cp_wait2();                  // stage kt complete
        __syncthreads();             // all warps done reading stage (kt+3)&3
        if (kt + 3 < nkt) load_kv((kt + 3) & 3, kt + 3);
        cp_commit();

        const uint32_t base = sb + 32768 + (kt & 3) * 32768;
        const bool active = (kt * 64 <= q0 + wm + 15);
        if (active) {
            // ---- S = Q K^T (3-term split) ----
            float sacc[8][4];
            #pragma unroll
            for (int j = 0; j < 8; j++)
                #pragma unroll
                for (int r = 0; r < 4; r++) sacc[j][r] = 0.0f;

            const int krow0 = (lane & 7) + ((lane >> 4) << 3);
            const int kgsel = (lane >> 3) & 1;
            #pragma unroll
            for (int kc = 0; kc < 4; kc++) {
                #pragma unroll
                for (int p = 0; p < 4; p++) {
                    const int row = p * 16 + krow0;
                    const uint32_t off = fswz(row, 2 * kc + kgsel);
                    uint32_t bh[4], bl[4];
                    ldsm4(bh, base + off);
                    ldsm4(bl, base + 8192 + off);
                    mma16816(sacc[2 * p],     qhf[kc], bh);
                    mma16816(sacc[2 * p + 1], qhf[kc], bh + 2);
                    mma16816(sacc[2 * p],     qlf[kc], bh);
                    mma16816(sacc[2 * p + 1], qlf[kc], bh + 2);
                    mma16816(sacc[2 * p],     qhf[kc], bl);
                    mma16816(sacc[2 * p + 1], qhf[kc], bl + 2);
                }
            }

            // ---- softmax ----
            const bool maskw = (kt * 64 + 63 > q0 + wm);
            float rmax0 = -1e30f, rmax8 = -1e30f;
            #pragma unroll
            for (int j = 0; j < 8; j++) {
                sacc[j][0] *= 0.125f; sacc[j][1] *= 0.125f;
                sacc[j][2] *= 0.125f; sacc[j][3] *= 0.125f;
                if (maskw) {
                    const int col = kt * 64 + j * 8 + ((lane & 3) << 1);
                    if (col     > qr0)     sacc[j][0] = -1e30f;
                    if (col + 1 > qr0)     sacc[j][1] = -1e30f;
                    if (col     > qr0 + 8) sacc[j][2] = -1e30f;
                    if (col + 1 > qr0 + 8) sacc[j][3] = -1e30f;
                }
                rmax0 = fmaxf(rmax0, fmaxf(sacc[j][0], sacc[j][1]));
                rmax8 = fmaxf(rmax8, fmaxf(sacc[j][2], sacc[j][3]));
            }
            rmax0 = fmaxf(rmax0, __shfl_xor_sync(0xffffffffu, rmax0, 1));
            rmax0 = fmaxf(rmax0, __shfl_xor_sync(0xffffffffu, rmax0, 2));
            rmax8 = fmaxf(rmax8, __shfl_xor_sync(0xffffffffu, rmax8, 1));
            rmax8 = fmaxf(rmax8, __shfl_xor_sync(0xffffffffu, rmax8, 2));

            const float mn0 = fmaxf(m0, rmax0), mn8 = fmaxf(m8, rmax8);
            const float a0 = __expf(m0 - mn0), a8 = __expf(m8 - mn8);
            m0 = mn0; m8 = mn8;

            float rs0 = 0.0f, rs8 = 0.0f;
            uint32_t ph[8][2], pl[8][2];
            #pragma unroll
            for (int j = 0; j < 8; j++) {
                const float p0 = __expf(sacc[j][0] - m0);
                const float p1 = __expf(sacc[j][1] - m0);
                const float p2 = __expf(sacc[j][2] - m8);
                const float p3 = __expf(sacc[j][3] - m8);
                rs0 += p0 + p1; rs8 += p2 + p3;
                __nv_bfloat16 b0, b1, b2, b3, r0b, r1b, r2b, r3b;
                split2(p0, b0, r0b); split2(p1, b1, r1b);
                split2(p2, b2, r2b); split2(p3, b3, r3b);
                ph[j][0] = pk2(b0, b1);  ph[j][1] = pk2(b2, b3);
                pl[j][0] = pk2(r0b, r1b); pl[j][1] = pk2(r2b, r3b);
            }
            rs0 += __shfl_xor_sync(0xffffffffu, rs0, 1);
            rs0 += __shfl_xor_sync(0xffffffffu, rs0, 2);
            rs8 += __shfl_xor_sync(0xffffffffu, rs8, 1);
            rs8 += __shfl_xor_sync(0xffffffffu, rs8, 2);
            l0 = l0 * a0 + rs0;
            l8 = l8 * a8 + rs8;

            #pragma unroll
            for (int j = 0; j < 8; j++) {
                oacc[j][0] *= a0; oacc[j][1] *= a0;
                oacc[j][2] *= a8; oacc[j][3] *= a8;
            }

            // ---- O += P V (3-term split) ----
            const int vrow0 = (lane & 7) + (((lane >> 3) & 1) << 3);
            const int vgsel = lane >> 4;
            #pragma unroll
            for (int kc = 0; kc < 4; kc++) {
                const uint32_t ah[4] = { ph[2 * kc][0], ph[2 * kc][1],
                                         ph[2 * kc + 1][0], ph[2 * kc + 1][1] };
                const uint32_t al[4] = { pl[2 * kc][0], pl[2 * kc][1],
                                         pl[2 * kc + 1][0], pl[2 * kc + 1][1] };
                const int row = kc * 16 + vrow0;
                #pragma unroll
                for (int gd = 0; gd < 4; gd++) {
                    const uint32_t off = fswz(row, 2 * gd + vgsel);
                    uint32_t vh[4], vl[4];
                    ldsm4t(vh, base + 16384 + off);
                    ldsm4t(vl, base + 24576 + off);
                    mma16816(oacc[2 * gd],     ah, vh);
                    mma16816(oacc[2 * gd + 1], ah, vh + 2);
                    mma16816(oacc[2 * gd],     al, vh);
                    mma16816(oacc[2 * gd + 1], al, vh + 2);
                    mma16816(oacc[2 * gd],     ah, vl);
                    mma16816(oacc[2 * gd + 1], ah, vl + 2);
                }
            }
        }
    }

    // ---- epilogue: normalize + write split-bf16 A2' (hi|lo|hi) ----
    const float inv0 = 1.0f / l0, inv8 = 1.0f / l8;
    const int row0 = q0 + wm + (lane >> 2);
    __nv_bfloat16* o0p = Out + (size_t)(b * Tn + row0) * K3 + h * 64 + ((lane & 3) << 1);
    __nv_bfloat16* o8p = o0p + (size_t)8 * K3;
    #pragma unroll
    for (int j = 0; j < 8; j++) {
        {
            const float v0 = oacc[j][0] * inv0, v1 = oacc[j][1] * inv0;
            __nv_bfloat16 h0, l0b, h1, l1b;
            split2(v0, h0, l0b); split2(v1, h1, l1b);
            *(uint32_t*)(o0p + j * 8)        = pk2(h0, h1);
            *(uint32_t*)(o0p + j * 8 + 1024) = pk2(l0b, l1b);
            *(uint32_t*)(o0p + j * 8 + 2048) = pk2(h0, h1);
        }
        {
            const float v0 = oacc[j][2] * inv8, v1 = oacc[j][3] * inv8;
            __nv_bfloat16 h0, l0b, h1, l1b;
            split2(v0, h0, l0b); split2(v1, h1, l1b);
            *(uint32_t*)(o8p + j * 8)        = pk2(h0, h1);
            *(uint32_t*)(o8p + j * 8 + 1024) = pk2(l0b, l1b);
            *(uint32_t*)(o8p + j * 8 + 2048) = pk2(h0, h1);
        }
    }
}

// ---------------------------------------------------------------------------
// Launch
// ---------------------------------------------------------------------------
extern "C" void kernel_launch(void* const* d_in, const int* in_sizes, int n_in,
                              void* d_out, int out_size)
{
    const float* x      = (const float*)d_in[0];
    const float* W_attn = (const float*)d_in[1];
    const float* b_attn = (const float*)d_in[2];
    const float* W_proj = (const float*)d_in[3];
    const float* b_proj = (const float*)d_in[4];
    float* out = (float*)d_out;

    __nv_bfloat16 *A1p, *B1p, *A2p, *B2p;
    __nv_bfloat16 *Qhp, *Qlp, *Khp, *Klp, *Vhp, *Vlp;
    cudaGetSymbolAddress((void**)&A1p, g_A1);
    cudaGetSymbolAddress((void**)&B1p, g_B1);
    cudaGetSymbolAddress((void**)&A2p, g_A2);
    cudaGetSymbolAddress((void**)&B2p, g_B2);
    cudaGetSymbolAddress((void**)&Qhp, g_Qh);
    cudaGetSymbolAddress((void**)&Qlp, g_Ql);
    cudaGetSymbolAddress((void**)&Khp, g_Kh);
    cudaGetSymbolAddress((void**)&Klp, g_Kl);
    cudaGetSymbolAddress((void**)&Vhp, g_Vh);
    cudaGetSymbolAddress((void**)&Vlp, g_Vl);

    const int GEMM_SMEM = 4 * 16384;   // 64KB, 4 stages
    cudaFuncSetAttribute(gemm_mma<0>, cudaFuncAttributeMaxDynamicSharedMemorySize, GEMM_SMEM);
    cudaFuncSetAttribute(gemm_mma<1>, cudaFuncAttributeMaxDynamicSharedMemorySize, GEMM_SMEM);

    // 0) Split/transpose prep
    split_x_kernel<<<(Mr * Cn / 4) / 256, 256>>>(x, A1p);
    tsplit_kernel<<<dim3(Cn / 32, (3 * Cn) / 32), dim3(32, 8)>>>(W_attn, B1p, 3 * Cn);
    tsplit_kernel<<<dim3(Cn / 32, Cn / 32), dim3(32, 8)>>>(W_proj, B2p, Cn);

    // 1) QKV projection (mma.sync), split-bf16 scatter to Qh/Ql/Kh/Kl/Vh/Vl
    gemm_mma<0><<<dim3((3 * Cn) / 128, Mr / 128), 256, GEMM_SMEM>>>(A1p, B1p, b_attn, nullptr);

    // 2) Tensorized causal flash attention -> split-bf16 A2'
    {
        const int smem = 32768 + 4 * 32768;   // Q tiles + 4 KV stages = 160KB
        cudaFuncSetAttribute(flash2, cudaFuncAttributeMaxDynamicSharedMemorySize, smem);
        dim3 grid(Tn / 128, Hn, Bn);
        flash2<<<grid, 256, smem>>>(Qhp, Qlp, Khp, Klp, Vhp, Vlp, A2p);
    }

    // 3) Output projection (mma.sync) -> d_out
    gemm_mma<1><<<dim3(Cn / 128, Mr / 128), 256, GEMM_SMEM>>>(A2p, B2p, b_proj, out);
}